// round 1
// baseline (speedup 1.0000x reference)
#include <cuda_runtime.h>
#include <math.h>

// Problem constants
#define NN    59392      // nodes
#define HIDD  256
#define DOUT  232
#define DH    116        // per-head dim
#define DEG   8
#define NB    512        // graphs
#define NPG   116        // nodes per graph
#define WCOLS 928        // 4 * 232 concatenated weight columns

// ---------------- scratch (device globals; no allocation allowed) ----------
__device__ float g_W[HIDD * WCOLS];                 // packed [256][928]
__device__ float g_q[(size_t)NN * DOUT];
__device__ float g_k[(size_t)NN * DOUT];
__device__ float g_v[(size_t)NN * DOUT];
__device__ float g_hp[(size_t)NN * DOUT];           // s projection, then += attn
__device__ float g_e[NN];
__device__ int   g_src64;

// ---------------- 0: detect int64 vs int32 edge_index ----------------------
__global__ void detect_kernel(const int* __restrict__ ei) {
    // If edge_index is int64 little-endian, the odd int32 words (high halves)
    // of the first 64 entries are all zero (values < 2^31). With int32 data
    // those words are src values of edges 1,3,5,... (random, ~never all 0).
    int all0 = 1;
    for (int i = 0; i < 64; i++) {
        if (ei[2 * i + 1] != 0) { all0 = 0; break; }
    }
    g_src64 = all0;
}

// ---------------- 1: pack [Wq|Wk|Wv|Ws] into g_W ---------------------------
__global__ void pack_w_kernel(const float* __restrict__ Wq, const float* __restrict__ Wk,
                              const float* __restrict__ Wv, const float* __restrict__ Ws) {
    int idx = blockIdx.x * blockDim.x + threadIdx.x;
    const int total = HIDD * WCOLS;
    for (; idx < total; idx += gridDim.x * blockDim.x) {
        int k = idx / WCOLS;
        int n = idx - k * WCOLS;
        float v;
        if (n < 232)      v = Wq[k * 232 + n];
        else if (n < 464) v = Wk[k * 232 + (n - 232)];
        else if (n < 696) v = Wv[k * 232 + (n - 464)];
        else              v = Ws[k * 232 + (n - 696)];
        g_W[idx] = v;
    }
}

// ---------------- 2: fused GEMM  P = h @ Wcat  -----------------------------
// BM=128, BN=64, BK=8, 256 threads, 8x4 microtile per thread.
#define BM 128
#define BN 64
#define BK 8

__global__ __launch_bounds__(256) void gemm_kernel(const float* __restrict__ A) {
    __shared__ float As[BK][BM];   // transposed A tile
    __shared__ float Bs[BK][BN];

    const int n0 = blockIdx.x * BN;   // x = N-block (15) so consecutive blocks reuse A rows
    const int m0 = blockIdx.y * BM;   // y = M-block (464)
    const int t  = threadIdx.x;
    const int tx = t & 15;            // 0..15 -> 4 cols each
    const int ty = t >> 4;            // 0..15 -> 8 rows each

    float acc[8][4];
#pragma unroll
    for (int i = 0; i < 8; i++)
#pragma unroll
        for (int j = 0; j < 4; j++) acc[i][j] = 0.0f;

    const int arow = t >> 1;          // 0..127
    const int akq  = (t & 1) * 4;     // 0 or 4
    const int bk   = t >> 5;          // 0..7
    const int bn   = (t & 31) * 2;    // 0..62

    for (int k0 = 0; k0 < HIDD; k0 += BK) {
        // load A tile (float4 along K), store transposed
        float4 av = *(const float4*)&A[(size_t)(m0 + arow) * HIDD + k0 + akq];
        As[akq + 0][arow] = av.x;
        As[akq + 1][arow] = av.y;
        As[akq + 2][arow] = av.z;
        As[akq + 3][arow] = av.w;
        // load B tile (2 scalars, bounds-checked vs 928)
        float b0 = 0.0f, b1 = 0.0f;
        if (n0 + bn < WCOLS)     b0 = g_W[(k0 + bk) * WCOLS + n0 + bn];
        if (n0 + bn + 1 < WCOLS) b1 = g_W[(k0 + bk) * WCOLS + n0 + bn + 1];
        Bs[bk][bn]     = b0;
        Bs[bk][bn + 1] = b1;
        __syncthreads();

#pragma unroll
        for (int kk = 0; kk < BK; kk++) {
            float4 bv  = *(const float4*)&Bs[kk][tx * 4];
            float4 a0v = *(const float4*)&As[kk][ty * 8];
            float4 a1v = *(const float4*)&As[kk][ty * 8 + 4];
            float a[8] = {a0v.x, a0v.y, a0v.z, a0v.w, a1v.x, a1v.y, a1v.z, a1v.w};
            float b[4] = {bv.x, bv.y, bv.z, bv.w};
#pragma unroll
            for (int i = 0; i < 8; i++)
#pragma unroll
                for (int j = 0; j < 4; j++) acc[i][j] = fmaf(a[i], b[j], acc[i][j]);
        }
        __syncthreads();
    }

    // route writes to q/k/v/hp
#pragma unroll
    for (int i = 0; i < 8; i++) {
        int row = m0 + ty * 8 + i;
#pragma unroll
        for (int j = 0; j < 4; j++) {
            int n = n0 + tx * 4 + j;
            if (n < WCOLS) {
                float* dst;
                int nn;
                if (n < 232)      { dst = g_q;  nn = n; }
                else if (n < 464) { dst = g_k;  nn = n - 232; }
                else if (n < 696) { dst = g_v;  nn = n - 464; }
                else              { dst = g_hp; nn = n - 696; }
                dst[(size_t)row * DOUT + nn] = acc[i][j];
            }
        }
    }
}

// ---------------- 3: per-node edge attention (+ mean e) --------------------
// One block (256 threads = 8 warps) per node; warp w handles edge w.
__global__ __launch_bounds__(256) void attn_kernel(const int* __restrict__ ei) {
    const int i = blockIdx.x;
    const int t = threadIdx.x;
    const int w = t >> 5, lane = t & 31;

    __shared__ float qs[DOUT];
    __shared__ float sc[2][8];
    __shared__ float al[2][8];
    __shared__ int   srcs[8];
    __shared__ float red[8];

    if (t < DOUT) qs[t] = g_q[(size_t)i * DOUT + t];
    if (t < DEG) {
        int e = i * DEG + t;
        srcs[t] = g_src64 ? ei[2 * e] : ei[e];
    }
    __syncthreads();

    // warp w: dot(q[i], k[src_w]) for both heads
    {
        int src = srcs[w];
        const float* kp = &g_k[(size_t)src * DOUT];
        float d0 = 0.0f, d1 = 0.0f;
        for (int c = lane; c < DH; c += 32) {
            d0 = fmaf(qs[c], kp[c], d0);
            d1 = fmaf(qs[DH + c], kp[DH + c], d1);
        }
#pragma unroll
        for (int o = 16; o > 0; o >>= 1) {
            d0 += __shfl_xor_sync(0xFFFFFFFFu, d0, o);
            d1 += __shfl_xor_sync(0xFFFFFFFFu, d1, o);
        }
        if (lane == 0) {
            const float s = 0.09284766908852593f;  // 1/sqrt(116)
            sc[0][w] = d0 * s;
            sc[1][w] = d1 * s;
        }
    }
    __syncthreads();

    // softmax over the 8 edges, per head (threads 0 and 1)
    if (t < 2) {
        float m = -1e30f;
#pragma unroll
        for (int j = 0; j < DEG; j++) m = fmaxf(m, sc[t][j]);
        float ex[DEG];
        float s = 0.0f;
#pragma unroll
        for (int j = 0; j < DEG; j++) { ex[j] = expf(sc[t][j] - m); s += ex[j]; }
        float inv = 1.0f / (s + 1e-16f);
#pragma unroll
        for (int j = 0; j < DEG; j++) al[t][j] = ex[j] * inv;
    }
    __syncthreads();

    // attn accumulate into h_proj (which already holds h@Ws), plus e = mean
    float part = 0.0f;
    for (int c = t; c < DOUT; c += 256) {
        int h = (c >= DH) ? 1 : 0;
        float acc = g_hp[(size_t)i * DOUT + c];
#pragma unroll
        for (int j = 0; j < DEG; j++)
            acc = fmaf(al[h][j], g_v[(size_t)srcs[j] * DOUT + c], acc);
        g_hp[(size_t)i * DOUT + c] = acc;
        part += acc;
    }
#pragma unroll
    for (int o = 16; o > 0; o >>= 1) part += __shfl_xor_sync(0xFFFFFFFFu, part, o);
    if (lane == 0) red[w] = part;
    __syncthreads();
    if (t == 0) {
        float s = 0.0f;
#pragma unroll
        for (int j = 0; j < 8; j++) s += red[j];
        g_e[i] = s * (1.0f / DOUT);
    }
}

// ---------------- 4: per-graph softmax + weighting -------------------------
__global__ __launch_bounds__(128) void final_kernel(float* __restrict__ out) {
    const int b = blockIdx.x;
    const int t = threadIdx.x;
    const int node0 = b * NPG;

    __shared__ float ev[128];
    __shared__ float al[NPG];

    float v = (t < NPG) ? g_e[node0 + t] : -1e30f;
    ev[t] = v;
    __syncthreads();
    for (int o = 64; o > 0; o >>= 1) {
        if (t < o) ev[t] = fmaxf(ev[t], ev[t + o]);
        __syncthreads();
    }
    float m = ev[0];
    __syncthreads();

    float ex = (t < NPG) ? expf(v - m) : 0.0f;
    ev[t] = ex;
    __syncthreads();
    for (int o = 64; o > 0; o >>= 1) {
        if (t < o) ev[t] += ev[t + o];
        __syncthreads();
    }
    float inv = 1.0f / ev[0];
    if (t < NPG) {
        float a = ex * inv;
        al[t] = a;
        out[node0 + t] = a;          // alpha_map
    }
    __syncthreads();

    float* hw = out + (size_t)NB * NPG;   // h_weighted
    const int total = NPG * DOUT;
    for (int idx = t; idx < total; idx += 128) {
        int nl = idx / DOUT;
        int c  = idx - nl * DOUT;
        size_t g = (size_t)(node0 + nl) * DOUT + c;
        hw[g] = al[nl] * g_hp[g];
    }
}

// ---------------- launch ----------------------------------------------------
extern "C" void kernel_launch(void* const* d_in, const int* in_sizes, int n_in,
                              void* d_out, int out_size) {
    (void)in_sizes; (void)n_in; (void)out_size;
    const float* h_flat = (const float*)d_in[0];
    const int*   ei     = (const int*)d_in[1];
    // d_in[2] = batch_index: unused (contiguous 116-node segments by construction)
    const float* Wq = (const float*)d_in[3];
    const float* Wk = (const float*)d_in[4];
    const float* Wv = (const float*)d_in[5];
    const float* Ws = (const float*)d_in[6];
    float* out = (float*)d_out;

    detect_kernel<<<1, 1>>>(ei);
    pack_w_kernel<<<232, 256>>>(Wq, Wk, Wv, Ws);
    gemm_kernel<<<dim3(15, 464), 256>>>(h_flat);
    attn_kernel<<<NN, 256>>>(ei);
    final_kernel<<<NB, 128>>>(out);
}

// round 5
// speedup vs baseline: 1.8954x; 1.8954x over previous
#include <cuda_runtime.h>
#include <cuda_bf16.h>
#include <math.h>
#include <stdint.h>

// Problem constants
#define NN    59392      // nodes
#define HIDD  256
#define DOUT  232
#define DH    116
#define DEG   8
#define NB    512
#define NPG   116
#define NPAD  960        // 15 * 64 padded output columns (4*232 = 928 real)
#define NTILES 15

// ---------------- scratch ----------------------------------------------------
__device__ __nv_bfloat16 g_Ahi[(size_t)NN * HIDD];
__device__ __nv_bfloat16 g_Alo[(size_t)NN * HIDD];
__device__ __nv_bfloat16 g_Whi[NPAD * HIDD];   // n-major: g_Whi[n*256 + k]
__device__ __nv_bfloat16 g_Wlo[NPAD * HIDD];
__device__ float g_q[(size_t)NN * DOUT];
__device__ float g_k[(size_t)NN * DOUT];
__device__ float g_v[(size_t)NN * DOUT];
__device__ float g_hp[(size_t)NN * DOUT];
__device__ float g_e[NN];
__device__ int   g_src64;

// ---------------- 0: detect int64 vs int32 edge_index ------------------------
__global__ void detect_kernel(const int* __restrict__ ei) {
    int all0 = 1;
    for (int i = 0; i < 64; i++)
        if (ei[2 * i + 1] != 0) { all0 = 0; break; }
    g_src64 = all0;
}

// ---------------- 1a: fp32 -> bf16 hi/lo split of h --------------------------
__global__ __launch_bounds__(256) void conv_h_kernel(const float* __restrict__ h) {
    int idx = blockIdx.x * blockDim.x + threadIdx.x;   // one float4 per thread
    const int total = NN * (HIDD / 4);
    if (idx >= total) return;
    float4 a = ((const float4*)h)[idx];
    __nv_bfloat16 h0 = __float2bfloat16(a.x), h1 = __float2bfloat16(a.y),
                  h2 = __float2bfloat16(a.z), h3 = __float2bfloat16(a.w);
    __nv_bfloat16 l0 = __float2bfloat16(a.x - __bfloat162float(h0));
    __nv_bfloat16 l1 = __float2bfloat16(a.y - __bfloat162float(h1));
    __nv_bfloat16 l2 = __float2bfloat16(a.z - __bfloat162float(h2));
    __nv_bfloat16 l3 = __float2bfloat16(a.w - __bfloat162float(h3));
    __nv_bfloat162 hv0 = {h0, h1}, hv1 = {h2, h3}, lv0 = {l0, l1}, lv1 = {l2, l3};
    uint2 hv = {*(uint32_t*)&hv0, *(uint32_t*)&hv1};
    uint2 lv = {*(uint32_t*)&lv0, *(uint32_t*)&lv1};
    ((uint2*)g_Ahi)[idx] = hv;
    ((uint2*)g_Alo)[idx] = lv;
}

// ---------------- 1b: pack W^T hi/lo, n-major [960][256] ---------------------
__global__ __launch_bounds__(256) void pack_w_kernel(const float* __restrict__ Wq,
                                                     const float* __restrict__ Wk,
                                                     const float* __restrict__ Wv,
                                                     const float* __restrict__ Ws) {
    int idx = blockIdx.x * blockDim.x + threadIdx.x;
    const int total = NPAD * HIDD;
    if (idx >= total) return;
    int n = idx / HIDD;
    int k = idx - n * HIDD;
    float v = 0.0f;
    if (n < 232)      v = Wq[k * 232 + n];
    else if (n < 464) v = Wk[k * 232 + (n - 232)];
    else if (n < 696) v = Wv[k * 232 + (n - 464)];
    else if (n < 928) v = Ws[k * 232 + (n - 696)];
    __nv_bfloat16 hi = __float2bfloat16(v);
    __nv_bfloat16 lo = __float2bfloat16(v - __bfloat162float(hi));
    g_Whi[idx] = hi;
    g_Wlo[idx] = lo;
}

// ---------------- 2: mma.sync split-bf16 GEMM --------------------------------
// 256 threads, 8 warps as 4(M)x2(N); warp tile 32x32; BM=128, BN=64, K resident.
// SMEM rows padded: 256 bf16 = 512B + 16B pad = 528B stride.
#define ROWB 528
#define SM_AHI 0
#define SM_ALO (128 * ROWB)                 //  67584
#define SM_BHI (2 * 128 * ROWB)             // 135168
#define SM_BLO (2 * 128 * ROWB + 64 * ROWB) // 168960
#define SM_TOTAL (2 * 128 * ROWB + 2 * 64 * ROWB)  // 202752

__device__ __forceinline__ void ldsm_x4(uint32_t* r, uint32_t addr) {
    asm volatile("ldmatrix.sync.aligned.m8n8.x4.shared.b16 {%0,%1,%2,%3}, [%4];"
                 : "=r"(r[0]), "=r"(r[1]), "=r"(r[2]), "=r"(r[3]) : "r"(addr));
}
__device__ __forceinline__ void mma_bf16(float* c, const uint32_t* a, const uint32_t* b) {
    asm volatile("mma.sync.aligned.m16n8k16.row.col.f32.bf16.bf16.f32 "
                 "{%0,%1,%2,%3}, {%4,%5,%6,%7}, {%8,%9}, {%0,%1,%2,%3};"
                 : "+f"(c[0]), "+f"(c[1]), "+f"(c[2]), "+f"(c[3])
                 : "r"(a[0]), "r"(a[1]), "r"(a[2]), "r"(a[3]), "r"(b[0]), "r"(b[1]));
}

__global__ __launch_bounds__(256, 1) void gemm_kernel() {
    extern __shared__ char smem[];
    const uint32_t sb = (uint32_t)__cvta_generic_to_shared(smem);
    const int t = threadIdx.x, wid = t >> 5, lane = t & 31;
    const int wm = wid & 3, wn = wid >> 2;     // warp coords: 4 x 2
    const int m0 = blockIdx.x * 128;

    // Load resident A tile (hi+lo), 128 rows x 512B, padded stride
    {
        const uint4* ahi = (const uint4*)g_Ahi;
        const uint4* alo = (const uint4*)g_Alo;
        for (int c = t; c < 4096; c += 256) {
            int r = c >> 5, ch = c & 31;
            size_t g = (size_t)(m0 + r) * 32 + ch;
            int d = r * ROWB + ch * 16;
            *(uint4*)(smem + SM_AHI + d) = ahi[g];
            *(uint4*)(smem + SM_ALO + d) = alo[g];
        }
    }

    // ldmatrix source addresses (byte offsets within padded tiles)
    // A (.x4): thread t: row = base + t%16, kbyte += (t/16)*16
    const int a_row = lane & 15;
    const int a_kof = (lane >> 4) * 16;
    // B (.x4 over 2 n-frags): g = t/8, r = t%8: n = nb + (g>>1)*8 + r, kbyte += (g&1)*16
    const int b_g = lane >> 3, b_r = lane & 7;
    const int b_n = (b_g >> 1) * 8 + b_r;
    const int b_kof = (b_g & 1) * 16;

    const uint4* whi = (const uint4*)g_Whi;
    const uint4* wlo = (const uint4*)g_Wlo;

    for (int j = 0; j < NTILES; j++) {
        // Load B tile (hi+lo): 64 rows x 512B
        for (int c = t; c < 2048; c += 256) {
            int r = c >> 5, ch = c & 31;
            size_t g = (size_t)(j * 64 + r) * 32 + ch;
            int d = r * ROWB + ch * 16;
            *(uint4*)(smem + SM_BHI + d) = whi[g];
            *(uint4*)(smem + SM_BLO + d) = wlo[g];
        }
        __syncthreads();

        float acc[2][4][4];
#pragma unroll
        for (int mf = 0; mf < 2; mf++)
#pragma unroll
            for (int nf = 0; nf < 4; nf++)
#pragma unroll
                for (int q = 0; q < 4; q++) acc[mf][nf][q] = 0.0f;

#pragma unroll
        for (int ks = 0; ks < 16; ks++) {
            const int kb = ks * 32;   // byte offset along K
            uint32_t ah[2][4], al[2][4], bh[2][4], bl[2][4];
#pragma unroll
            for (int mf = 0; mf < 2; mf++) {
                uint32_t ad = sb + (wm * 32 + mf * 16 + a_row) * ROWB + kb + a_kof;
                ldsm_x4(ah[mf], ad + SM_AHI);
                ldsm_x4(al[mf], ad + SM_ALO);
            }
#pragma unroll
            for (int nh = 0; nh < 2; nh++) {   // each covers n-frags 2nh, 2nh+1
                uint32_t bd = sb + (wn * 32 + nh * 16 + b_n) * ROWB + kb + b_kof;
                ldsm_x4(bh[nh], bd + SM_BHI);
                ldsm_x4(bl[nh], bd + SM_BLO);
            }
#pragma unroll
            for (int mf = 0; mf < 2; mf++)
#pragma unroll
                for (int nf = 0; nf < 4; nf++) {
                    const uint32_t* Bh = &bh[nf >> 1][(nf & 1) * 2];
                    const uint32_t* Bl = &bl[nf >> 1][(nf & 1) * 2];
                    mma_bf16(acc[mf][nf], ah[mf], Bh);
                    mma_bf16(acc[mf][nf], al[mf], Bh);
                    mma_bf16(acc[mf][nf], ah[mf], Bl);
                }
        }

        // Epilogue: C frag (m16n8): rows lane/4 (+8), cols 2*(lane%4)
        const int lr = lane >> 2, lc = (lane & 3) * 2;
#pragma unroll
        for (int mf = 0; mf < 2; mf++) {
            const int mbase = m0 + wm * 32 + mf * 16 + lr;
#pragma unroll
            for (int nf = 0; nf < 4; nf++) {
                const int n = j * 64 + wn * 32 + nf * 8 + lc;
                float* dst; int nn;
                if (n < 232)      { dst = g_q;  nn = n; }
                else if (n < 464) { dst = g_k;  nn = n - 232; }
                else if (n < 696) { dst = g_v;  nn = n - 464; }
                else if (n < 928) { dst = g_hp; nn = n - 696; }
                else continue;
                float2 v0 = {acc[mf][nf][0], acc[mf][nf][1]};
                float2 v1 = {acc[mf][nf][2], acc[mf][nf][3]};
                *(float2*)(dst + (size_t)mbase * DOUT + nn)       = v0;
                *(float2*)(dst + (size_t)(mbase + 8) * DOUT + nn) = v1;
            }
        }
        __syncthreads();
    }
}

// ---------------- 3: per-node edge attention (+ mean e), 64 threads ----------
__global__ __launch_bounds__(64) void attn_kernel(const int* __restrict__ ei) {
    const int i = blockIdx.x;
    const int t = threadIdx.x, w = t >> 5, lane = t & 31;

    __shared__ float4 qs4[58];
    __shared__ int    srcs[8];
    __shared__ float  sc[2][8];
    __shared__ float  al[2][8];
    __shared__ float  red[2];

    const float4* q4 = (const float4*)(g_q + (size_t)i * DOUT);
    if (t < 58) qs4[t] = q4[t];
    if (t < DEG) {
        int e = i * DEG + t;
        srcs[t] = g_src64 ? ei[2 * e] : ei[e];
    }
    __syncthreads();

#pragma unroll
    for (int je = 0; je < 4; je++) {
        const int eidx = w * 4 + je;
        const float4* kp4 = (const float4*)(g_k + (size_t)srcs[eidx] * DOUT);
        float d0 = 0.0f, d1 = 0.0f;
        if (lane < 29) {
            float4 qa = qs4[lane],      ka = kp4[lane];
            float4 qb = qs4[29 + lane], kb = kp4[29 + lane];
            d0 = qa.x*ka.x + qa.y*ka.y + qa.z*ka.z + qa.w*ka.w;
            d1 = qb.x*kb.x + qb.y*kb.y + qb.z*kb.z + qb.w*kb.w;
        }
#pragma unroll
        for (int o = 16; o > 0; o >>= 1) {
            d0 += __shfl_xor_sync(0xFFFFFFFFu, d0, o);
            d1 += __shfl_xor_sync(0xFFFFFFFFu, d1, o);
        }
        if (lane == 0) {
            const float s = 0.09284766908852593f;   // 1/sqrt(116)
            sc[0][eidx] = d0 * s;
            sc[1][eidx] = d1 * s;
        }
    }
    __syncthreads();

    if (t < 2) {
        float m = -1e30f;
#pragma unroll
        for (int jj = 0; jj < DEG; jj++) m = fmaxf(m, sc[t][jj]);
        float ex[DEG], s = 0.0f;
#pragma unroll
        for (int jj = 0; jj < DEG; jj++) { ex[jj] = expf(sc[t][jj] - m); s += ex[jj]; }
        float inv = 1.0f / (s + 1e-16f);
#pragma unroll
        for (int jj = 0; jj < DEG; jj++) al[t][jj] = ex[jj] * inv;
    }
    __syncthreads();

    float part = 0.0f;
    if (t < 58) {
        float4* hp4 = (float4*)(g_hp + (size_t)i * DOUT);
        float4 acc = hp4[t];
        const int h = (t >= 29) ? 1 : 0;
#pragma unroll
        for (int jj = 0; jj < DEG; jj++) {
            float a = al[h][jj];
            float4 vv = ((const float4*)(g_v + (size_t)srcs[jj] * DOUT))[t];
            acc.x = fmaf(a, vv.x, acc.x);
            acc.y = fmaf(a, vv.y, acc.y);
            acc.z = fmaf(a, vv.z, acc.z);
            acc.w = fmaf(a, vv.w, acc.w);
        }
        hp4[t] = acc;
        part = acc.x + acc.y + acc.z + acc.w;
    }
#pragma unroll
    for (int o = 16; o > 0; o >>= 1) part += __shfl_xor_sync(0xFFFFFFFFu, part, o);
    if (lane == 0) red[w] = part;
    __syncthreads();
    if (t == 0) g_e[i] = (red[0] + red[1]) * (1.0f / DOUT);
}

// ---------------- 4: per-graph softmax + weighting ---------------------------
__global__ __launch_bounds__(128) void final_kernel(float* __restrict__ out) {
    const int b = blockIdx.x;
    const int t = threadIdx.x;
    const int node0 = b * NPG;

    __shared__ float ev[128];
    __shared__ float al[NPG];

    float v = (t < NPG) ? g_e[node0 + t] : -1e30f;
    ev[t] = v;
    __syncthreads();
    for (int o = 64; o > 0; o >>= 1) {
        if (t < o) ev[t] = fmaxf(ev[t], ev[t + o]);
        __syncthreads();
    }
    float m = ev[0];
    __syncthreads();
    float ex = (t < NPG) ? expf(v - m) : 0.0f;
    ev[t] = ex;
    __syncthreads();
    for (int o = 64; o > 0; o >>= 1) {
        if (t < o) ev[t] += ev[t + o];
        __syncthreads();
    }
    float inv = 1.0f / ev[0];
    if (t < NPG) {
        float a = ex * inv;
        al[t] = a;
        out[node0 + t] = a;
    }
    __syncthreads();

    float4* hw4 = (float4*)(out + (size_t)NB * NPG);
    const float4* hp4 = (const float4*)g_hp;
    const int total = NPG * 58;
    for (int idx = t; idx < total; idx += 128) {
        int nl = idx / 58;
        int c  = idx - nl * 58;
        size_t g = (size_t)(node0 + nl) * 58 + c;
        float4 x = hp4[g];
        float a = al[nl];
        float4 y = {a * x.x, a * x.y, a * x.z, a * x.w};
        hw4[g] = y;
    }
}

// ---------------- launch -----------------------------------------------------
extern "C" void kernel_launch(void* const* d_in, const int* in_sizes, int n_in,
                              void* d_out, int out_size) {
    (void)in_sizes; (void)n_in; (void)out_size;
    const float* h_flat = (const float*)d_in[0];
    const int*   ei     = (const int*)d_in[1];
    const float* Wq = (const float*)d_in[3];
    const float* Wk = (const float*)d_in[4];
    const float* Wv = (const float*)d_in[5];
    const float* Ws = (const float*)d_in[6];
    float* out = (float*)d_out;

    cudaFuncSetAttribute(gemm_kernel, cudaFuncAttributeMaxDynamicSharedMemorySize, SM_TOTAL);

    detect_kernel<<<1, 1>>>(ei);
    conv_h_kernel<<<(NN * 64 + 255) / 256, 256>>>(h_flat);
    pack_w_kernel<<<(NPAD * HIDD + 255) / 256, 256>>>(Wq, Wk, Wv, Ws);
    gemm_kernel<<<464, 256, SM_TOTAL>>>();
    attn_kernel<<<NN, 64>>>(ei);
    final_kernel<<<NB, 128>>>(out);
}